// round 1
// baseline (speedup 1.0000x reference)
#include <cuda_runtime.h>
#include <cstdint>

// BlockLinear: out = block_diag(blocks) @ inp + bias
//   inp:    (2048, 8192) f32   row-major
//   blocks: (8, 256, 256) f32
//   bias:   (2048,) f32
//   out:    (2048, 8192) f32
//
// 8 independent GEMMs: C_k[256,8192] = A_k[256,256] @ B_k[256,8192] + bias.
// fp32 tiled SGEMM with packed fma.rn.f32x2 (2 lanes per FFMA issue slot).

#define BM 128
#define BN 128
#define BK 16
#define NT (256 / BK)   // 16 K-tiles

typedef unsigned long long u64;
typedef unsigned int u32;

__device__ __forceinline__ void ffma2(u64& d, u64 a, u64 b) {
    asm("fma.rn.f32x2 %0, %1, %2, %0;" : "+l"(d) : "l"(a), "l"(b));
}

__device__ __forceinline__ u64 dup_f32(float x) {
    u32 u = __float_as_uint(x);
    return ((u64)u << 32) | (u64)u;
}

__device__ __forceinline__ float lo_f32(u64 v) { return __uint_as_float((u32)v); }
__device__ __forceinline__ float hi_f32(u64 v) { return __uint_as_float((u32)(v >> 32)); }

__global__ __launch_bounds__(256, 2)
void block_linear_kernel(const float* __restrict__ inp,
                         const float* __restrict__ blocks,
                         const float* __restrict__ bias,
                         float* __restrict__ out)
{
    // A tile stored pre-duplicated: As2[k][m] = (a, a) as f32x2 -> no packing in inner loop.
    __shared__ __align__(16) u64   As2[2][BK][BM];   // 2*16*128*8  = 32 KB
    __shared__ __align__(16) float Bs [2][BK][BN];   // 2*16*128*4  = 16 KB

    const int kblk  = blockIdx.z;      // 0..7   which diagonal block
    const int mTile = blockIdx.y;      // 0..1
    const int nTile = blockIdx.x;      // 0..63

    const float* A = blocks + kblk * (256 * 256) + mTile * BM * 256;   // [128,256], row stride 256
    const float* B = inp + (size_t)(kblk * 256) * 8192 + nTile * BN;   // [256,128], row stride 8192
    float*       C = out + (size_t)(kblk * 256 + mTile * BM) * 8192 + nTile * BN;
    const float* biasp = bias + kblk * 256 + mTile * BM;

    const int tid = threadIdx.x;
    const int tx  = tid & 15;          // 0..15 -> n
    const int ty  = tid >> 4;          // 0..15 -> m

    // Loader mapping
    const int a_m  = tid >> 1;         // 0..127
    const int a_kh = (tid & 1) * 8;    // 0 or 8
    const int b_r  = tid >> 4;         // 0..15
    const int b_c  = (tid & 15) * 4;   // 0,4,...,60

    float4 pa0, pa1, pb0, pb1;         // global prefetch registers

    u64 acc[8][4];
    #pragma unroll
    for (int i = 0; i < 8; i++)
        #pragma unroll
        for (int j = 0; j < 4; j++) acc[i][j] = 0ull;

    // ---- prologue: load tile 0 ----
    {
        const float* Ap = A + a_m * 256 + a_kh;
        pa0 = *(const float4*)(Ap);
        pa1 = *(const float4*)(Ap + 4);
        const float* Bp = B + (size_t)b_r * 8192 + b_c;
        pb0 = *(const float4*)(Bp);
        pb1 = *(const float4*)(Bp + 64);
    }
    {
        // store A duplicated+transposed
        As2[0][a_kh + 0][a_m] = dup_f32(pa0.x);
        As2[0][a_kh + 1][a_m] = dup_f32(pa0.y);
        As2[0][a_kh + 2][a_m] = dup_f32(pa0.z);
        As2[0][a_kh + 3][a_m] = dup_f32(pa0.w);
        As2[0][a_kh + 4][a_m] = dup_f32(pa1.x);
        As2[0][a_kh + 5][a_m] = dup_f32(pa1.y);
        As2[0][a_kh + 6][a_m] = dup_f32(pa1.z);
        As2[0][a_kh + 7][a_m] = dup_f32(pa1.w);
        *(float4*)&Bs[0][b_r][b_c]      = pb0;
        *(float4*)&Bs[0][b_r][b_c + 64] = pb1;
    }
    __syncthreads();

    #pragma unroll 1
    for (int t = 0; t < NT; ++t) {
        const int cur = t & 1;

        // prefetch next tile from global
        if (t + 1 < NT) {
            const float* Ap = A + a_m * 256 + (t + 1) * BK + a_kh;
            pa0 = *(const float4*)(Ap);
            pa1 = *(const float4*)(Ap + 4);
            const float* Bp = B + (size_t)((t + 1) * BK + b_r) * 8192 + b_c;
            pb0 = *(const float4*)(Bp);
            pb1 = *(const float4*)(Bp + 64);
        }

        // ---- compute on current buffer ----
        #pragma unroll
        for (int kk = 0; kk < BK; ++kk) {
            // a: 8 duplicated f32x2 values (m = ty*4..+3 and 64+ty*4..+3)
            ulonglong2 a01 = *(const ulonglong2*)&As2[cur][kk][ty * 4];
            ulonglong2 a23 = *(const ulonglong2*)&As2[cur][kk][ty * 4 + 2];
            ulonglong2 a45 = *(const ulonglong2*)&As2[cur][kk][64 + ty * 4];
            ulonglong2 a67 = *(const ulonglong2*)&As2[cur][kk][64 + ty * 4 + 2];
            // b: 8 floats = 4 natural f32x2 pairs (n = tx*4..+3 and 64+tx*4..+3)
            ulonglong2 b01 = *(const ulonglong2*)&Bs[cur][kk][tx * 4];
            ulonglong2 b23 = *(const ulonglong2*)&Bs[cur][kk][64 + tx * 4];

            u64 av[8] = {a01.x, a01.y, a23.x, a23.y, a45.x, a45.y, a67.x, a67.y};
            u64 bv[4] = {b01.x, b01.y, b23.x, b23.y};

            #pragma unroll
            for (int i = 0; i < 8; i++)
                #pragma unroll
                for (int j = 0; j < 4; j++)
                    ffma2(acc[i][j], av[i], bv[j]);
        }
        __syncthreads();

        // store prefetched tile into the other buffer
        if (t + 1 < NT) {
            const int nxt = 1 - cur;
            As2[nxt][a_kh + 0][a_m] = dup_f32(pa0.x);
            As2[nxt][a_kh + 1][a_m] = dup_f32(pa0.y);
            As2[nxt][a_kh + 2][a_m] = dup_f32(pa0.z);
            As2[nxt][a_kh + 3][a_m] = dup_f32(pa0.w);
            As2[nxt][a_kh + 4][a_m] = dup_f32(pa1.x);
            As2[nxt][a_kh + 5][a_m] = dup_f32(pa1.y);
            As2[nxt][a_kh + 6][a_m] = dup_f32(pa1.z);
            As2[nxt][a_kh + 7][a_m] = dup_f32(pa1.w);
            *(float4*)&Bs[nxt][b_r][b_c]      = pb0;
            *(float4*)&Bs[nxt][b_r][b_c + 64] = pb1;
            __syncthreads();
        }
    }

    // ---- epilogue: add bias, store ----
    #pragma unroll
    for (int i = 0; i < 8; i++) {
        const int m = (i < 4) ? (ty * 4 + i) : (64 + ty * 4 + (i - 4));
        const float bv = __ldg(biasp + m);
        float4 o0, o1;
        o0.x = lo_f32(acc[i][0]) + bv;
        o0.y = hi_f32(acc[i][0]) + bv;
        o0.z = lo_f32(acc[i][1]) + bv;
        o0.w = hi_f32(acc[i][1]) + bv;
        o1.x = lo_f32(acc[i][2]) + bv;
        o1.y = hi_f32(acc[i][2]) + bv;
        o1.z = lo_f32(acc[i][3]) + bv;
        o1.w = hi_f32(acc[i][3]) + bv;
        *(float4*)(C + (size_t)m * 8192 + tx * 4)      = o0;
        *(float4*)(C + (size_t)m * 8192 + 64 + tx * 4) = o1;
    }
}

extern "C" void kernel_launch(void* const* d_in, const int* in_sizes, int n_in,
                              void* d_out, int out_size)
{
    const float* inp    = (const float*)d_in[0];   // (2048, 8192)
    const float* blocks = (const float*)d_in[1];   // (8, 256, 256)
    const float* bias   = (const float*)d_in[2];   // (2048,)
    float* out          = (float*)d_out;           // (2048, 8192)

    dim3 grid(8192 / BN, 256 / BM, 8);  // (64, 2, 8)
    block_linear_kernel<<<grid, 256>>>(inp, blocks, bias, out);
}

// round 4
// speedup vs baseline: 1.6543x; 1.6543x over previous
#include <cuda_runtime.h>
#include <cuda_bf16.h>
#include <cstdint>

// BlockLinear: out = block_diag(blocks) @ inp + bias (fp32 in/out)
// Tensor-core path via warp-level mma.sync bf16 (target-agnostic PTX; tcgen05
// is unavailable because the harness ptxas targets sm_103 w/o the 'a' suffix).
// Emulated fp32: x = hi(bf16) + lo(bf16); C = ah*bh + ah*bl + al*bh  (~1e-5 rel err)
//
// CTA: 128(M) x 128(N), K=256 in 8 chunks of 32, double-buffered smem.
// 8 warps (4m x 2n), warp tile 32x64, m16n8k16 HMMA.

typedef unsigned int u32;

#define BK 32
#define STAGE_STRIDE 32768     // Ah 8K | Al 8K | Bh 8K | Bl 8K
#define OFF_AH 0
#define OFF_AL 8192
#define OFF_BH 16384
#define OFF_BL 24576
#define SMEM_BYTES (2 * STAGE_STRIDE)

__device__ __forceinline__ u32 smem_u32(const void* p) {
    u32 a;
    asm("{ .reg .u64 t; cvta.to.shared.u64 t, %1; cvt.u32.u64 %0, t; }" : "=r"(a) : "l"(p));
    return a;
}

// smem tile: 128 rows x 32 bf16 (64B rows, 4 chunks of 16B), XOR swizzle on
// chunk index with (row>>1)&3 -> ldmatrix 8-row phases hit 8 distinct bank groups.
__device__ __forceinline__ u32 soff(u32 r, u32 k) {
    return r * 64u + ((((k >> 3) ^ ((r >> 1) & 3u))) << 4) + ((k & 7u) << 1);
}

__device__ __forceinline__ void ldsm4(u32& r0, u32& r1, u32& r2, u32& r3, u32 addr) {
    asm volatile("ldmatrix.sync.aligned.m8n8.x4.shared.b16 {%0,%1,%2,%3}, [%4];"
                 : "=r"(r0), "=r"(r1), "=r"(r2), "=r"(r3) : "r"(addr));
}

__device__ __forceinline__ void mma16816(float* c, const u32* a, u32 b0, u32 b1) {
    asm volatile(
        "mma.sync.aligned.m16n8k16.row.col.f32.bf16.bf16.f32 "
        "{%0,%1,%2,%3}, {%4,%5,%6,%7}, {%8,%9}, {%0,%1,%2,%3};"
        : "+f"(c[0]), "+f"(c[1]), "+f"(c[2]), "+f"(c[3])
        : "r"(a[0]), "r"(a[1]), "r"(a[2]), "r"(a[3]), "r"(b0), "r"(b1));
}

__device__ __forceinline__ void split2(float x0, float x1, u32& hp, u32& lp) {
    __nv_bfloat16 h0 = __float2bfloat16(x0);
    __nv_bfloat16 h1 = __float2bfloat16(x1);
    float r0 = x0 - __bfloat162float(h0);
    float r1 = x1 - __bfloat162float(h1);
    __nv_bfloat16 l0 = __float2bfloat16(r0);
    __nv_bfloat16 l1 = __float2bfloat16(r1);
    hp = (u32)__bfloat16_as_ushort(h0) | ((u32)__bfloat16_as_ushort(h1) << 16);
    lp = (u32)__bfloat16_as_ushort(l0) | ((u32)__bfloat16_as_ushort(l1) << 16);
}

__global__ __launch_bounds__(256)
void block_linear_hmma(const float* __restrict__ inp,
                       const float* __restrict__ blocks,
                       const float* __restrict__ bias,
                       float* __restrict__ out)
{
    extern __shared__ char smem[];
    const u32 sb = smem_u32(smem);

    const int tid  = threadIdx.x;
    const int lane = tid & 31;
    const int wid  = tid >> 5;
    const int wm   = wid & 3;       // 4 warp rows x 32
    const int wn   = wid >> 2;      // 2 warp cols x 64

    const int kblk  = blockIdx.z;
    const int mTile = blockIdx.y;
    const int nTile = blockIdx.x;

    const float* A = blocks + (size_t)kblk * 65536 + (size_t)mTile * 128 * 256;
    const float* B = inp + (size_t)(kblk * 256) * 8192 + nTile * 128;
    float*       C = out + (size_t)(kblk * 256 + mTile * 128) * 8192 + nTile * 128;
    const float* biasp = bias + kblk * 256 + mTile * 128;

    // loader mappings
    const int ar = tid >> 2;            // A row 0..63 (+64 second pass)
    const int ac = (tid & 3) * 8;       // A k-offset {0,8,16,24}
    const int bn = tid & 127;           // B column within tile
    const int bkg = (tid >> 7) * 2;     // first of 2 k-groups handled

    float aR[16], bR[16];

    float acc[2][8][4];
    #pragma unroll
    for (int i = 0; i < 2; i++)
        #pragma unroll
        for (int j = 0; j < 8; j++)
            #pragma unroll
            for (int q = 0; q < 4; q++) acc[i][j][q] = 0.f;

    // ---- load chunk c into registers ----
    auto load_regs = [&](int c) {
        const float* ap = A + (size_t)ar * 256 + c * BK + ac;
        float4 v;
        v = *(const float4*)(ap);          aR[0]=v.x; aR[1]=v.y; aR[2]=v.z; aR[3]=v.w;
        v = *(const float4*)(ap + 4);      aR[4]=v.x; aR[5]=v.y; aR[6]=v.z; aR[7]=v.w;
        v = *(const float4*)(ap + 64*256);     aR[8]=v.x; aR[9]=v.y; aR[10]=v.z; aR[11]=v.w;
        v = *(const float4*)(ap + 64*256 + 4); aR[12]=v.x; aR[13]=v.y; aR[14]=v.z; aR[15]=v.w;
        const float* bp = B + (size_t)(c * BK + bkg * 8) * 8192 + bn;
        #pragma unroll
        for (int i = 0; i < 8; i++) bR[i] = bp[(size_t)i * 8192];
        bp += (size_t)8 * 8192;
        #pragma unroll
        for (int i = 0; i < 8; i++) bR[8 + i] = bp[(size_t)i * 8192];
    };

    // ---- split + store regs to smem stage ----
    auto store_stage = [&](int c) {
        char* buf = smem + (c & 1) * STAGE_STRIDE;
        #pragma unroll
        for (int it = 0; it < 2; it++) {
            u32 h[4], l[4];
            split2(aR[it*8+0], aR[it*8+1], h[0], l[0]);
            split2(aR[it*8+2], aR[it*8+3], h[1], l[1]);
            split2(aR[it*8+4], aR[it*8+5], h[2], l[2]);
            split2(aR[it*8+6], aR[it*8+7], h[3], l[3]);
            const u32 o = soff((u32)(ar + it * 64), (u32)ac);
            *(uint4*)(buf + OFF_AH + o) = make_uint4(h[0], h[1], h[2], h[3]);
            *(uint4*)(buf + OFF_AL + o) = make_uint4(l[0], l[1], l[2], l[3]);
        }
        #pragma unroll
        for (int g = 0; g < 2; g++) {
            u32 h[4], l[4];
            split2(bR[g*8+0], bR[g*8+1], h[0], l[0]);
            split2(bR[g*8+2], bR[g*8+3], h[1], l[1]);
            split2(bR[g*8+4], bR[g*8+5], h[2], l[2]);
            split2(bR[g*8+6], bR[g*8+7], h[3], l[3]);
            const u32 o = soff((u32)bn, (u32)((bkg + g) * 8));
            *(uint4*)(buf + OFF_BH + o) = make_uint4(h[0], h[1], h[2], h[3]);
            *(uint4*)(buf + OFF_BL + o) = make_uint4(l[0], l[1], l[2], l[3]);
        }
    };

    // ---- compute one chunk from smem stage ----
    auto compute = [&](int c) {
        const u32 buf = sb + (u32)(c & 1) * STAGE_STRIDE;
        #pragma unroll
        for (int kk = 0; kk < 2; kk++) {
            const u32 krow = (u32)(kk * 16 + ((lane >> 4) << 3));
            // A rows for this lane
            const u32 am = (u32)(wm * 32 + (lane & 15));
            const u32 bnr = (u32)(wn * 64 + (lane & 15));

            u32 aH[2][4], aL[2][4], bH[4][4], bL[4][4];
            #pragma unroll
            for (int i = 0; i < 2; i++)
                ldsm4(aH[i][0], aH[i][1], aH[i][2], aH[i][3],
                      buf + OFF_AH + soff(am + i * 16, krow));
            #pragma unroll
            for (int p = 0; p < 4; p++)
                ldsm4(bH[p][0], bH[p][1], bH[p][2], bH[p][3],
                      buf + OFF_BH + soff(bnr + p * 16, krow));
            // hh
            #pragma unroll
            for (int i = 0; i < 2; i++)
                #pragma unroll
                for (int p = 0; p < 4; p++) {
                    mma16816(acc[i][2*p],   aH[i], bH[p][0], bH[p][2]);
                    mma16816(acc[i][2*p+1], aH[i], bH[p][1], bH[p][3]);
                }
            // hl
            #pragma unroll
            for (int p = 0; p < 4; p++)
                ldsm4(bL[p][0], bL[p][1], bL[p][2], bL[p][3],
                      buf + OFF_BL + soff(bnr + p * 16, krow));
            #pragma unroll
            for (int i = 0; i < 2; i++)
                #pragma unroll
                for (int p = 0; p < 4; p++) {
                    mma16816(acc[i][2*p],   aH[i], bL[p][0], bL[p][2]);
                    mma16816(acc[i][2*p+1], aH[i], bL[p][1], bL[p][3]);
                }
            // lh
            #pragma unroll
            for (int i = 0; i < 2; i++)
                ldsm4(aL[i][0], aL[i][1], aL[i][2], aL[i][3],
                      buf + OFF_AL + soff(am + i * 16, krow));
            #pragma unroll
            for (int i = 0; i < 2; i++)
                #pragma unroll
                for (int p = 0; p < 4; p++) {
                    mma16816(acc[i][2*p],   aL[i], bH[p][0], bH[p][2]);
                    mma16816(acc[i][2*p+1], aL[i], bH[p][1], bH[p][3]);
                }
        }
    };

    load_regs(0);
    store_stage(0);
    __syncthreads();

    #pragma unroll 1
    for (int c = 0; c < 8; ++c) {
        if (c < 7) load_regs(c + 1);
        compute(c);
        __syncthreads();
        if (c < 7) {
            store_stage(c + 1);
            __syncthreads();
        }
    }

    // ---- epilogue: bias + store ----
    #pragma unroll
    for (int i = 0; i < 2; i++) {
        const int r0 = wm * 32 + i * 16 + (lane >> 2);
        const float b0 = biasp[r0];
        const float b1 = biasp[r0 + 8];
        float* p0 = C + (size_t)r0 * 8192;
        float* p1 = C + (size_t)(r0 + 8) * 8192;
        #pragma unroll
        for (int j = 0; j < 8; j++) {
            const int col = wn * 64 + j * 8 + (lane & 3) * 2;
            float2 v0 = make_float2(acc[i][j][0] + b0, acc[i][j][1] + b0);
            float2 v1 = make_float2(acc[i][j][2] + b1, acc[i][j][3] + b1);
            *(float2*)(p0 + col) = v0;
            *(float2*)(p1 + col) = v1;
        }
    }
}

extern "C" void kernel_launch(void* const* d_in, const int* in_sizes, int n_in,
                              void* d_out, int out_size)
{
    const float* inp    = (const float*)d_in[0];   // (2048, 8192)
    const float* blocks = (const float*)d_in[1];   // (8, 256, 256)
    const float* bias   = (const float*)d_in[2];   // (2048,)
    float* out          = (float*)d_out;           // (2048, 8192)

    static int configured = 0;
    if (!configured) {
        cudaFuncSetAttribute(block_linear_hmma,
                             cudaFuncAttributeMaxDynamicSharedMemorySize, SMEM_BYTES);
        configured = 1;
    }
    dim3 grid(64, 2, 8);
    block_linear_hmma<<<grid, 256, SMEM_BYTES>>>(inp, blocks, bias, out);
}

// round 7
// speedup vs baseline: 2.0317x; 1.2282x over previous
#include <cuda_runtime.h>
#include <cuda_fp16.h>
#include <cstdint>

// BlockLinear: out = block_diag(blocks) @ inp + bias (fp32 in/out)
// 3-kernel plan:
//   k1: inp (2048,8192) fp32 -> BhT (8192,2048) fp16, transposed (n-major, k-contig)
//   kA: blocks -> Ah, Al fp16 (hi/lo split, same [m][k] layout)
//   k2: GEMM C = (Ah+Al) @ Bh^T + bias via mma.sync f16 (2 MMA terms),
//       cp.async 4-stage pipeline, 2 CTAs/SM.
// Error: only B rounding to fp16 -> global RMS rel err ~1.4e-4 (<1e-3).

typedef unsigned int u32;

// ---------------- scratch (static device memory; no allocation) ----------------
__device__ __half g_Ah[8 * 256 * 256];
__device__ __half g_Al[8 * 256 * 256];
__device__ __half g_BhT[8192 * 2048];   // [n][k]

__device__ __forceinline__ u32 smem_u32(const void* p) {
    u32 a;
    asm("{ .reg .u64 t; cvta.to.shared.u64 t, %1; cvt.u32.u64 %0, t; }" : "=r"(a) : "l"(p));
    return a;
}

// ---------------- kernel 1: convert + transpose B ----------------
// tile: 128 k-rows x 128 n-cols; smem [n][k2] u32(half2), 16B-chunk swizzled
__global__ __launch_bounds__(256)
void convert_transpose_B(const float* __restrict__ inp)
{
    __shared__ u32 st[128 * 64];
    const int t = threadIdx.x;
    const int k0 = blockIdx.x * 128;
    const int n0 = blockIdx.y * 128;

    // load: thread -> col n_loc, 64 rows (half of tile)
    {
        const int n_loc = t & 127;
        const int half = t >> 7;
        const float* src = inp + (size_t)(k0 + half * 64) * 8192 + n0 + n_loc;
        #pragma unroll
        for (int kk = 0; kk < 32; ++kk) {
            float x0 = src[(size_t)(2 * kk) * 8192];
            float x1 = src[(size_t)(2 * kk + 1) * 8192];
            __half2 h2 = __floats2half2_rn(x0, x1);
            const int c = half * 32 + kk;                    // u32 index 0..63
            const int idx = n_loc * 64 + ((((c >> 2) ^ (n_loc & 15)) << 2) | (c & 3));
            st[idx] = *reinterpret_cast<u32*>(&h2);
        }
    }
    __syncthreads();
    // store: thread -> row n_loc = t>>1, 8 chunks of 16B (contiguous 128B)
    {
        const int n_loc = t >> 1;
        const int cq0 = (t & 1) * 8;
        __half* dst = g_BhT + (size_t)(n0 + n_loc) * 2048 + k0;
        #pragma unroll
        for (int j = 0; j < 8; ++j) {
            const int cq = cq0 + j;
            uint4 v = *(const uint4*)&st[n_loc * 64 + ((cq ^ (n_loc & 15)) << 2)];
            *(uint4*)(dst + cq * 8) = v;
        }
    }
}

// ---------------- kernel A: split blocks into Ah + Al ----------------
__global__ __launch_bounds__(256)
void split_A(const float* __restrict__ blocks)
{
    const int base = (blockIdx.x * 256 + threadIdx.x) * 4;
    float4 v = *(const float4*)(blocks + base);
    __half h0 = __float2half_rn(v.x), h1 = __float2half_rn(v.y);
    __half h2 = __float2half_rn(v.z), h3 = __float2half_rn(v.w);
    __half l0 = __float2half_rn(v.x - __half2float(h0));
    __half l1 = __float2half_rn(v.y - __half2float(h1));
    __half l2 = __float2half_rn(v.z - __half2float(h2));
    __half l3 = __float2half_rn(v.w - __half2float(h3));
    uint2 ph, pl;
    ph.x = (u32)__half_as_ushort(h0) | ((u32)__half_as_ushort(h1) << 16);
    ph.y = (u32)__half_as_ushort(h2) | ((u32)__half_as_ushort(h3) << 16);
    pl.x = (u32)__half_as_ushort(l0) | ((u32)__half_as_ushort(l1) << 16);
    pl.y = (u32)__half_as_ushort(l2) | ((u32)__half_as_ushort(l3) << 16);
    *(uint2*)(g_Ah + base) = ph;
    *(uint2*)(g_Al + base) = pl;
}

// ---------------- kernel 2: GEMM ----------------
#define BK 32
#define OFF_AH 0
#define OFF_AL 8192
#define OFF_BH 16384
#define STAGE_STRIDE 24576
#define NSTAGE 4
#define SMEM_BYTES (NSTAGE * STAGE_STRIDE)   // 96 KB

// 128x32 fp16 tile, 64B rows, 4x16B chunks, XOR swizzle (verified round-4)
__device__ __forceinline__ u32 soff(u32 r, u32 k) {
    return r * 64u + ((((k >> 3) ^ ((r >> 1) & 3u))) << 4) + ((k & 7u) << 1);
}
__device__ __forceinline__ u32 schunk(u32 r, u32 c) {
    return r * 64u + ((c ^ ((r >> 1) & 3u)) << 4);
}

__device__ __forceinline__ void ldsm4(u32& r0, u32& r1, u32& r2, u32& r3, u32 addr) {
    asm volatile("ldmatrix.sync.aligned.m8n8.x4.shared.b16 {%0,%1,%2,%3}, [%4];"
                 : "=r"(r0), "=r"(r1), "=r"(r2), "=r"(r3) : "r"(addr));
}
__device__ __forceinline__ void mma16816(float* c, const u32* a, u32 b0, u32 b1) {
    asm volatile(
        "mma.sync.aligned.m16n8k16.row.col.f32.f16.f16.f32 "
        "{%0,%1,%2,%3}, {%4,%5,%6,%7}, {%8,%9}, {%0,%1,%2,%3};"
        : "+f"(c[0]), "+f"(c[1]), "+f"(c[2]), "+f"(c[3])
        : "r"(a[0]), "r"(a[1]), "r"(a[2]), "r"(a[3]), "r"(b0), "r"(b1));
}
__device__ __forceinline__ void cp16(u32 dst, const void* src) {
    asm volatile("cp.async.cg.shared.global [%0], [%1], 16;" :: "r"(dst), "l"(src));
}

__global__ __launch_bounds__(256, 2)
void block_linear_gemm(const float* __restrict__ bias, float* __restrict__ out)
{
    extern __shared__ char smem[];
    const u32 sb = smem_u32(smem);

    const int tid  = threadIdx.x;
    const int lane = tid & 31;
    const int wid  = tid >> 5;
    const int wm   = wid & 3;       // 4 warp rows x 32
    const int wn   = wid >> 2;      // 2 warp cols x 64

    const int kblk  = blockIdx.z;
    const int mTile = blockIdx.y;
    const int nTile = blockIdx.x;

    const __half* Agh = g_Ah + (size_t)kblk * 65536 + (size_t)mTile * 128 * 256;
    const __half* Agl = g_Al + (size_t)kblk * 65536 + (size_t)mTile * 128 * 256;
    const __half* Bg  = g_BhT + (size_t)(nTile * 128) * 2048 + kblk * 256;
    float*        C   = out + (size_t)(kblk * 256 + mTile * 128) * 8192 + nTile * 128;
    const float* biasp = bias + kblk * 256 + mTile * 128;

    // loader: thread -> row r = tid>>1, chunks (tid&1)*2 + {0,1}
    const int lr = tid >> 1;
    const int lc = (tid & 1) * 2;

    float acc[2][8][4];
    #pragma unroll
    for (int i = 0; i < 2; i++)
        #pragma unroll
        for (int j = 0; j < 8; j++)
            #pragma unroll
            for (int q = 0; q < 4; q++) acc[i][j][q] = 0.f;

    auto load_stage = [&](int c) {
        const u32 st = sb + (u32)(c & (NSTAGE - 1)) * STAGE_STRIDE;
        const int k0 = c * BK;
        #pragma unroll
        for (int j = 0; j < 2; ++j) {
            const int ch = lc + j;
            const u32 d = schunk((u32)lr, (u32)ch);
            cp16(st + OFF_AH + d, Agh + (size_t)lr * 256 + k0 + ch * 8);
            cp16(st + OFF_AL + d, Agl + (size_t)lr * 256 + k0 + ch * 8);
            cp16(st + OFF_BH + d, Bg + (size_t)lr * 2048 + k0 + ch * 8);
        }
    };

    // prologue: stages 0..2
    load_stage(0); asm volatile("cp.async.commit_group;" ::: "memory");
    load_stage(1); asm volatile("cp.async.commit_group;" ::: "memory");
    load_stage(2); asm volatile("cp.async.commit_group;" ::: "memory");

    #pragma unroll 1
    for (int c = 0; c < 8; ++c) {
        asm volatile("cp.async.wait_group 2;" ::: "memory");
        __syncthreads();

        const u32 buf = sb + (u32)(c & (NSTAGE - 1)) * STAGE_STRIDE;
        #pragma unroll
        for (int kk = 0; kk < 2; ++kk) {
            const u32 krow = (u32)(kk * 16 + ((lane >> 4) << 3));
            const u32 am  = (u32)(wm * 32 + (lane & 15));
            const u32 bnr = (u32)(wn * 64 + (lane & 15));

            u32 aH[2][4], aL[2][4], bH[4][4];
            #pragma unroll
            for (int i = 0; i < 2; i++)
                ldsm4(aH[i][0], aH[i][1], aH[i][2], aH[i][3],
                      buf + OFF_AH + soff(am + i * 16, krow));
            #pragma unroll
            for (int p = 0; p < 4; p++)
                ldsm4(bH[p][0], bH[p][1], bH[p][2], bH[p][3],
                      buf + OFF_BH + soff(bnr + p * 16, krow));
            #pragma unroll
            for (int i = 0; i < 2; i++)
                #pragma unroll
                for (int p = 0; p < 4; p++) {
                    mma16816(acc[i][2*p],   aH[i], bH[p][0], bH[p][2]);
                    mma16816(acc[i][2*p+1], aH[i], bH[p][1], bH[p][3]);
                }
            #pragma unroll
            for (int i = 0; i < 2; i++)
                ldsm4(aL[i][0], aL[i][1], aL[i][2], aL[i][3],
                      buf + OFF_AL + soff(am + i * 16, krow));
            #pragma unroll
            for (int i = 0; i < 2; i++)
                #pragma unroll
                for (int p = 0; p < 4; p++) {
                    mma16816(acc[i][2*p],   aL[i], bH[p][0], bH[p][2]);
                    mma16816(acc[i][2*p+1], aL[i], bH[p][1], bH[p][3]);
                }
        }
        __syncthreads();
        if (c + 3 < 8) load_stage(c + 3);
        asm volatile("cp.async.commit_group;" ::: "memory");  // empty commits keep count uniform
    }

    // epilogue: bias + store (verified round-4 mapping)
    #pragma unroll
    for (int i = 0; i < 2; i++) {
        const int r0 = wm * 32 + i * 16 + (lane >> 2);
        const float b0 = biasp[r0];
        const float b1 = biasp[r0 + 8];
        float* p0 = C + (size_t)r0 * 8192;
        float* p1 = C + (size_t)(r0 + 8) * 8192;
        #pragma unroll
        for (int j = 0; j < 8; j++) {
            const int col = wn * 64 + j * 8 + (lane & 3) * 2;
            *(float2*)(p0 + col) = make_float2(acc[i][j][0] + b0, acc[i][j][1] + b0);
            *(float2*)(p1 + col) = make_float2(acc[i][j][2] + b1, acc[i][j][3] + b1);
        }
    }
}

extern "C" void kernel_launch(void* const* d_in, const int* in_sizes, int n_in,
                              void* d_out, int out_size)
{
    const float* inp    = (const float*)d_in[0];   // (2048, 8192)
    const float* blocks = (const float*)d_in[1];   // (8, 256, 256)
    const float* bias   = (const float*)d_in[2];   // (2048,)
    float* out          = (float*)d_out;           // (2048, 8192)

    static int configured = 0;
    if (!configured) {
        cudaFuncSetAttribute(block_linear_gemm,
                             cudaFuncAttributeMaxDynamicSharedMemorySize, SMEM_BYTES);
        configured = 1;
    }

    dim3 g1(2048 / 128, 8192 / 128);              // 16 x 64
    convert_transpose_B<<<g1, 256>>>(inp);
    split_A<<<512, 256>>>(blocks);
    dim3 g2(64, 2, 8);
    block_linear_gemm<<<g2, 256, SMEM_BYTES>>>(bias, out);
}

// round 8
// speedup vs baseline: 2.6910x; 1.3245x over previous
#include <cuda_runtime.h>
#include <cuda_fp16.h>
#include <cstdint>

// BlockLinear: out = block_diag(blocks) @ inp + bias (fp32 in/out)
//   k1: inp (2048,8192) f32 -> BhT (8192,2048) fp16 transposed (swizzled smem, ~2-way max)
//   kA: blocks -> Ah fp16
//   k2: GEMM C = Ah @ BhT^T + bias via mma.sync f16, cp.async 4-stage, 1 sync/iter.
// Error: A and B each rounded once to fp16 -> global RMS rel err ~3e-4 (<1e-3).

typedef unsigned int u32;

__device__ __half g_Ah[8 * 256 * 256];
__device__ __half g_BhT[8192 * 2048];   // [n][k]

__device__ __forceinline__ u32 smem_u32(const void* p) {
    u32 a;
    asm("{ .reg .u64 t; cvta.to.shared.u64 t, %1; cvt.u32.u64 %0, t; }" : "=r"(a) : "l"(p));
    return a;
}

// ---------------- kernel 1: convert + transpose B (conflict-fixed) ----------------
// tile 128 k x 128 n; smem logical [row=n][c=0..63 u32], 16B-chunk XOR swizzle by row&15.
__global__ __launch_bounds__(256)
void convert_transpose_B(const float* __restrict__ inp)
{
    __shared__ u32 st[128 * 64];
    const int t = threadIdx.x;
    const int k0 = blockIdx.x * 128;
    const int n0 = blockIdx.y * 128;

    // load phase: thread -> column n_loc, half of k-rows
    {
        const int n_loc = t & 127;
        const int half = t >> 7;
        const float* src = inp + (size_t)(k0 + half * 64) * 8192 + n0 + n_loc;
        #pragma unroll
        for (int kk = 0; kk < 32; ++kk) {
            float x0 = src[(size_t)(2 * kk) * 8192];
            float x1 = src[(size_t)(2 * kk + 1) * 8192];
            __half2 h2 = __floats2half2_rn(x0, x1);
            const int c = half * 32 + kk;                          // u32 col 0..63
            const int cp = ((c >> 2) ^ (n_loc & 15));              // swizzled 16B chunk
            st[n_loc * 64 + cp * 4 + (c & 3)] = *reinterpret_cast<u32*>(&h2);
        }
    }
    __syncthreads();
    // store phase: thread -> row n_loc = t>>1, 8 x 16B chunks
    {
        const int row = t >> 1;
        const int cq0 = (t & 1) * 8;
        __half* dst = g_BhT + (size_t)(n0 + row) * 2048 + k0;
        #pragma unroll
        for (int j = 0; j < 8; ++j) {
            const int cq = cq0 + j;
            uint4 v = *(const uint4*)&st[row * 64 + ((cq ^ (row & 15)) << 2)];
            *(uint4*)(dst + cq * 8) = v;
        }
    }
}

// ---------------- kernel A: convert blocks -> Ah fp16 ----------------
__global__ __launch_bounds__(256)
void split_A(const float* __restrict__ blocks)
{
    const int base = (blockIdx.x * 256 + threadIdx.x) * 4;
    float4 v = *(const float4*)(blocks + base);
    __half2 h01 = __floats2half2_rn(v.x, v.y);
    __half2 h23 = __floats2half2_rn(v.z, v.w);
    uint2 ph;
    ph.x = *reinterpret_cast<u32*>(&h01);
    ph.y = *reinterpret_cast<u32*>(&h23);
    *(uint2*)(g_Ah + base) = ph;
}

// ---------------- kernel 2: GEMM ----------------
#define BK 32
#define OFF_AH 0
#define OFF_BH 8192
#define STAGE_STRIDE 16384
#define NSTAGE 4
#define SMEM_BYTES (NSTAGE * STAGE_STRIDE)   // 64 KB

// 128x32 fp16 tile, 64B rows, 4x16B chunks, XOR swizzle (verified round-4/7)
__device__ __forceinline__ u32 soff(u32 r, u32 k) {
    return r * 64u + ((((k >> 3) ^ ((r >> 1) & 3u))) << 4) + ((k & 7u) << 1);
}
__device__ __forceinline__ u32 schunk(u32 r, u32 c) {
    return r * 64u + ((c ^ ((r >> 1) & 3u)) << 4);
}

__device__ __forceinline__ void ldsm4(u32& r0, u32& r1, u32& r2, u32& r3, u32 addr) {
    asm volatile("ldmatrix.sync.aligned.m8n8.x4.shared.b16 {%0,%1,%2,%3}, [%4];"
                 : "=r"(r0), "=r"(r1), "=r"(r2), "=r"(r3) : "r"(addr));
}
__device__ __forceinline__ void mma16816(float* c, const u32* a, u32 b0, u32 b1) {
    asm volatile(
        "mma.sync.aligned.m16n8k16.row.col.f32.f16.f16.f32 "
        "{%0,%1,%2,%3}, {%4,%5,%6,%7}, {%8,%9}, {%0,%1,%2,%3};"
        : "+f"(c[0]), "+f"(c[1]), "+f"(c[2]), "+f"(c[3])
        : "r"(a[0]), "r"(a[1]), "r"(a[2]), "r"(a[3]), "r"(b0), "r"(b1));
}
__device__ __forceinline__ void cp16(u32 dst, const void* src) {
    asm volatile("cp.async.cg.shared.global [%0], [%1], 16;" :: "r"(dst), "l"(src));
}

__global__ __launch_bounds__(256, 2)
void block_linear_gemm(const float* __restrict__ bias, float* __restrict__ out)
{
    extern __shared__ char smem[];
    const u32 sb = smem_u32(smem);

    const int tid  = threadIdx.x;
    const int lane = tid & 31;
    const int wid  = tid >> 5;
    const int wm   = wid & 3;       // 4 warp rows x 32
    const int wn   = wid >> 2;      // 2 warp cols x 64

    const int kblk  = blockIdx.z;
    const int mTile = blockIdx.y;
    const int nTile = blockIdx.x;

    const __half* Agh = g_Ah + (size_t)kblk * 65536 + (size_t)mTile * 128 * 256;
    const __half* Bg  = g_BhT + (size_t)(nTile * 128) * 2048 + kblk * 256;
    float*        C   = out + (size_t)(kblk * 256 + mTile * 128) * 8192 + nTile * 128;
    const float* biasp = bias + kblk * 256 + mTile * 128;

    const int lr = tid >> 1;            // smem row 0..127
    const int lc = (tid & 1) * 2;       // first of 2 chunks

    float acc[2][8][4];
    #pragma unroll
    for (int i = 0; i < 2; i++)
        #pragma unroll
        for (int j = 0; j < 8; j++)
            #pragma unroll
            for (int q = 0; q < 4; q++) acc[i][j][q] = 0.f;

    auto load_stage = [&](int c) {
        const u32 st = sb + (u32)(c & (NSTAGE - 1)) * STAGE_STRIDE;
        const int k0 = c * BK;
        #pragma unroll
        for (int j = 0; j < 2; ++j) {
            const int ch = lc + j;
            const u32 d = schunk((u32)lr, (u32)ch);
            cp16(st + OFF_AH + d, Agh + (size_t)lr * 256 + k0 + ch * 8);
            cp16(st + OFF_BH + d, Bg + (size_t)lr * 2048 + k0 + ch * 8);
        }
    };

    load_stage(0); asm volatile("cp.async.commit_group;" ::: "memory");
    load_stage(1); asm volatile("cp.async.commit_group;" ::: "memory");
    load_stage(2); asm volatile("cp.async.commit_group;" ::: "memory");

    #pragma unroll 1
    for (int c = 0; c < 8; ++c) {
        asm volatile("cp.async.wait_group 2;" ::: "memory");
        __syncthreads();

        // overwrites slot (c+3)&3 == (c-1)&3, consumed at iter c-1; the sync
        // above proves all warps finished compute(c-1) -> safe, loads overlap MMA.
        if (c + 3 < 8) load_stage(c + 3);
        asm volatile("cp.async.commit_group;" ::: "memory");

        const u32 buf = sb + (u32)(c & (NSTAGE - 1)) * STAGE_STRIDE;
        #pragma unroll
        for (int kk = 0; kk < 2; ++kk) {
            const u32 krow = (u32)(kk * 16 + ((lane >> 4) << 3));
            const u32 am  = (u32)(wm * 32 + (lane & 15));
            const u32 bnr = (u32)(wn * 64 + (lane & 15));

            u32 aH[2][4], bH[4][4];
            #pragma unroll
            for (int i = 0; i < 2; i++)
                ldsm4(aH[i][0], aH[i][1], aH[i][2], aH[i][3],
                      buf + OFF_AH + soff(am + i * 16, krow));
            #pragma unroll
            for (int p = 0; p < 4; p++)
                ldsm4(bH[p][0], bH[p][1], bH[p][2], bH[p][3],
                      buf + OFF_BH + soff(bnr + p * 16, krow));
            #pragma unroll
            for (int i = 0; i < 2; i++)
                #pragma unroll
                for (int p = 0; p < 4; p++) {
                    mma16816(acc[i][2*p],   aH[i], bH[p][0], bH[p][2]);
                    mma16816(acc[i][2*p+1], aH[i], bH[p][1], bH[p][3]);
                }
        }
    }

    // epilogue: bias + store (verified mapping)
    #pragma unroll
    for (int i = 0; i < 2; i++) {
        const int r0 = wm * 32 + i * 16 + (lane >> 2);
        const float b0 = biasp[r0];
        const float b1 = biasp[r0 + 8];
        float* p0 = C + (size_t)r0 * 8192;
        float* p1 = C + (size_t)(r0 + 8) * 8192;
        #pragma unroll
        for (int j = 0; j < 8; j++) {
            const int col = wn * 64 + j * 8 + (lane & 3) * 2;
            *(float2*)(p0 + col) = make_float2(acc[i][j][0] + b0, acc[i][j][1] + b0);
            *(float2*)(p1 + col) = make_float2(acc[i][j][2] + b1, acc[i][j][3] + b1);
        }
    }
}

extern "C" void kernel_launch(void* const* d_in, const int* in_sizes, int n_in,
                              void* d_out, int out_size)
{
    const float* inp    = (const float*)d_in[0];   // (2048, 8192)
    const float* blocks = (const float*)d_in[1];   // (8, 256, 256)
    const float* bias   = (const float*)d_in[2];   // (2048,)
    float* out          = (float*)d_out;           // (2048, 8192)

    static int configured = 0;
    if (!configured) {
        cudaFuncSetAttribute(block_linear_gemm,
                             cudaFuncAttributeMaxDynamicSharedMemorySize, SMEM_BYTES);
        configured = 1;
    }

    dim3 g1(2048 / 128, 8192 / 128);              // 16 x 64
    convert_transpose_B<<<g1, 256>>>(inp);
    split_A<<<512, 256>>>(blocks);
    dim3 g2(64, 2, 8);
    block_linear_gemm<<<g2, 256, SMEM_BYTES>>>(bias, out);
}

// round 9
// speedup vs baseline: 3.4108x; 1.2674x over previous
#include <cuda_runtime.h>
#include <cuda_fp16.h>
#include <cstdint>

// BlockLinear: out = block_diag(blocks) @ inp + bias (fp32 in/out)
//   k1: inp (2048,8192) f32 -> g_Bh (2048,8192) fp16  (pure elementwise stream)
//   kA: blocks -> g_Ah fp16
//   k2: GEMM C = Ah @ Bh + bias via mma.sync f16; A frags non-trans ldmatrix,
//       B frags ldmatrix.trans on [k][n] tiles; cp.async 4-stage, 1 sync/iter.
// Error: A and B each rounded once to fp16 -> global RMS rel err ~2.9e-4 (<1e-3).

typedef unsigned int u32;

__device__ __half g_Ah[8 * 256 * 256];
__device__ __half g_Bh[2048 * 8192];   // [k][n] fp16

__device__ __forceinline__ u32 smem_u32(const void* p) {
    u32 a;
    asm("{ .reg .u64 t; cvta.to.shared.u64 t, %1; cvt.u32.u64 %0, t; }" : "=r"(a) : "l"(p));
    return a;
}

// ---------------- kernel 1: elementwise fp32 -> fp16 ----------------
__global__ __launch_bounds__(256)
void convert_B(const float* __restrict__ inp)
{
    const size_t i = ((size_t)blockIdx.x * 256 + threadIdx.x) * 8;
    float4 v0 = *(const float4*)(inp + i);
    float4 v1 = *(const float4*)(inp + i + 4);
    __half2 h0 = __floats2half2_rn(v0.x, v0.y);
    __half2 h1 = __floats2half2_rn(v0.z, v0.w);
    __half2 h2 = __floats2half2_rn(v1.x, v1.y);
    __half2 h3 = __floats2half2_rn(v1.z, v1.w);
    uint4 o;
    o.x = *reinterpret_cast<u32*>(&h0);
    o.y = *reinterpret_cast<u32*>(&h1);
    o.z = *reinterpret_cast<u32*>(&h2);
    o.w = *reinterpret_cast<u32*>(&h3);
    *(uint4*)(g_Bh + i) = o;
}

// ---------------- kernel A: blocks -> fp16 ----------------
__global__ __launch_bounds__(256)
void split_A(const float* __restrict__ blocks)
{
    const int base = (blockIdx.x * 256 + threadIdx.x) * 4;
    float4 v = *(const float4*)(blocks + base);
    __half2 h01 = __floats2half2_rn(v.x, v.y);
    __half2 h23 = __floats2half2_rn(v.z, v.w);
    uint2 ph;
    ph.x = *reinterpret_cast<u32*>(&h01);
    ph.y = *reinterpret_cast<u32*>(&h23);
    *(uint2*)(g_Ah + base) = ph;
}

// ---------------- kernel 2: GEMM ----------------
#define BK 32
#define OFF_AH 0
#define OFF_B  8192
#define STAGE_STRIDE 16384
#define NSTAGE 4
#define SMEM_BYTES (NSTAGE * STAGE_STRIDE)   // 64 KB

// A tile: 128 m-rows x 32 k, 64B rows, 4x16B chunks, XOR swizzle (verified)
__device__ __forceinline__ u32 soff(u32 r, u32 k) {
    return r * 64u + ((((k >> 3) ^ ((r >> 1) & 3u))) << 4) + ((k & 7u) << 1);
}
__device__ __forceinline__ u32 schunk(u32 r, u32 c) {
    return r * 64u + ((c ^ ((r >> 1) & 3u)) << 4);
}
// B tile: 32 k-rows x 128 n halves, 256B rows, 16x16B chunks, chunk ^= (k&7)
__device__ __forceinline__ u32 bchunk(u32 k, u32 nc) {
    return k * 256u + ((nc ^ (k & 7u)) << 4);
}

__device__ __forceinline__ void ldsm4(u32& r0, u32& r1, u32& r2, u32& r3, u32 addr) {
    asm volatile("ldmatrix.sync.aligned.m8n8.x4.shared.b16 {%0,%1,%2,%3}, [%4];"
                 : "=r"(r0), "=r"(r1), "=r"(r2), "=r"(r3) : "r"(addr));
}
__device__ __forceinline__ void ldsm4t(u32& r0, u32& r1, u32& r2, u32& r3, u32 addr) {
    asm volatile("ldmatrix.sync.aligned.m8n8.x4.trans.shared.b16 {%0,%1,%2,%3}, [%4];"
                 : "=r"(r0), "=r"(r1), "=r"(r2), "=r"(r3) : "r"(addr));
}
__device__ __forceinline__ void mma16816(float* c, const u32* a, u32 b0, u32 b1) {
    asm volatile(
        "mma.sync.aligned.m16n8k16.row.col.f32.f16.f16.f32 "
        "{%0,%1,%2,%3}, {%4,%5,%6,%7}, {%8,%9}, {%0,%1,%2,%3};"
        : "+f"(c[0]), "+f"(c[1]), "+f"(c[2]), "+f"(c[3])
        : "r"(a[0]), "r"(a[1]), "r"(a[2]), "r"(a[3]), "r"(b0), "r"(b1));
}
__device__ __forceinline__ void cp16(u32 dst, const void* src) {
    asm volatile("cp.async.cg.shared.global [%0], [%1], 16;" :: "r"(dst), "l"(src));
}

__global__ __launch_bounds__(256, 2)
void block_linear_gemm(const float* __restrict__ bias, float* __restrict__ out)
{
    extern __shared__ char smem[];
    const u32 sb = smem_u32(smem);

    const int tid  = threadIdx.x;
    const int lane = tid & 31;
    const int wid  = tid >> 5;
    const int wm   = wid & 3;       // 4 warp rows x 32
    const int wn   = wid >> 2;      // 2 warp cols x 64

    const int kblk  = blockIdx.z;
    const int mTile = blockIdx.y;
    const int nTile = blockIdx.x;
    const int n0    = nTile * 128;

    const __half* Agh = g_Ah + (size_t)kblk * 65536 + (size_t)mTile * 128 * 256;
    const __half* Bg  = g_Bh + (size_t)(kblk * 256) * 8192 + n0;
    float*        C   = out + (size_t)(kblk * 256 + mTile * 128) * 8192 + n0;
    const float* biasp = bias + kblk * 256 + mTile * 128;

    // A loader: row = tid>>1, 2 chunks of 16B
    const int alr = tid >> 1;
    const int alc = (tid & 1) * 2;
    // B loader: row k = tid>>3, chunks (tid&7)*2 + {0,1}
    const int blk_r = tid >> 3;
    const int blc   = (tid & 7) * 2;

    float acc[2][8][4];
    #pragma unroll
    for (int i = 0; i < 2; i++)
        #pragma unroll
        for (int j = 0; j < 8; j++)
            #pragma unroll
            for (int q = 0; q < 4; q++) acc[i][j][q] = 0.f;

    auto load_stage = [&](int c) {
        const u32 st = sb + (u32)(c & (NSTAGE - 1)) * STAGE_STRIDE;
        const int k0 = c * BK;
        #pragma unroll
        for (int j = 0; j < 2; ++j) {
            const int ch = alc + j;
            cp16(st + OFF_AH + schunk((u32)alr, (u32)ch),
                 Agh + (size_t)alr * 256 + k0 + ch * 8);
            const int nc = blc + j;
            cp16(st + OFF_B + bchunk((u32)blk_r, (u32)nc),
                 Bg + (size_t)(k0 + blk_r) * 8192 + nc * 8);
        }
    };

    load_stage(0); asm volatile("cp.async.commit_group;" ::: "memory");
    load_stage(1); asm volatile("cp.async.commit_group;" ::: "memory");
    load_stage(2); asm volatile("cp.async.commit_group;" ::: "memory");

    // B ldmatrix.trans per-lane address components (constant over loop):
    //   k_lane_off = ((lane>>4)<<3) + (lane&7), nc_lane = (lane>>3)&1
    const u32 kl  = (u32)(((lane >> 4) << 3) + (lane & 7));
    const u32 ncl = (u32)((lane >> 3) & 1);

    #pragma unroll 1
    for (int c = 0; c < 8; ++c) {
        asm volatile("cp.async.wait_group 2;" ::: "memory");
        __syncthreads();

        if (c + 3 < 8) load_stage(c + 3);
        asm volatile("cp.async.commit_group;" ::: "memory");

        const u32 buf = sb + (u32)(c & (NSTAGE - 1)) * STAGE_STRIDE;
        #pragma unroll
        for (int kk = 0; kk < 2; ++kk) {
            const u32 krow = (u32)(kk * 16);
            const u32 am   = (u32)(wm * 32 + (lane & 15));
            const u32 akr  = krow + (u32)((lane >> 4) << 3);

            u32 aH[2][4], bH[4][4];
            #pragma unroll
            for (int i = 0; i < 2; i++)
                ldsm4(aH[i][0], aH[i][1], aH[i][2], aH[i][3],
                      buf + OFF_AH + soff(am + i * 16, akr));
            #pragma unroll
            for (int p = 0; p < 4; p++) {
                const u32 ncb = (u32)(wn * 8 + p * 2) + ncl;
                ldsm4t(bH[p][0], bH[p][1], bH[p][2], bH[p][3],
                       buf + OFF_B + bchunk(krow + kl, ncb));
            }
            #pragma unroll
            for (int i = 0; i < 2; i++)
                #pragma unroll
                for (int p = 0; p < 4; p++) {
                    mma16816(acc[i][2*p],   aH[i], bH[p][0], bH[p][2]);
                    mma16816(acc[i][2*p+1], aH[i], bH[p][1], bH[p][3]);
                }
        }
    }

    // epilogue: bias + store (verified mapping)
    #pragma unroll
    for (int i = 0; i < 2; i++) {
        const int r0 = wm * 32 + i * 16 + (lane >> 2);
        const float b0 = biasp[r0];
        const float b1 = biasp[r0 + 8];
        float* p0 = C + (size_t)r0 * 8192;
        float* p1 = C + (size_t)(r0 + 8) * 8192;
        #pragma unroll
        for (int j = 0; j < 8; j++) {
            const int col = wn * 64 + j * 8 + (lane & 3) * 2;
            *(float2*)(p0 + col) = make_float2(acc[i][j][0] + b0, acc[i][j][1] + b0);
            *(float2*)(p1 + col) = make_float2(acc[i][j][2] + b1, acc[i][j][3] + b1);
        }
    }
}

extern "C" void kernel_launch(void* const* d_in, const int* in_sizes, int n_in,
                              void* d_out, int out_size)
{
    const float* inp    = (const float*)d_in[0];   // (2048, 8192)
    const float* blocks = (const float*)d_in[1];   // (8, 256, 256)
    const float* bias   = (const float*)d_in[2];   // (2048,)
    float* out          = (float*)d_out;           // (2048, 8192)

    static int configured = 0;
    if (!configured) {
        cudaFuncSetAttribute(block_linear_gemm,
                             cudaFuncAttributeMaxDynamicSharedMemorySize, SMEM_BYTES);
        configured = 1;
    }

    convert_B<<<8192, 256>>>(inp);                // 2048*8192 / (256*8)
    split_A<<<512, 256>>>(blocks);
    dim3 g2(64, 2, 8);
    block_linear_gemm<<<g2, 256, SMEM_BYTES>>>(bias, out);
}

// round 12
// speedup vs baseline: 3.7027x; 1.0856x over previous
#include <cuda_runtime.h>
#include <cuda_fp16.h>
#include <cstdint>

// BlockLinear: out = block_diag(blocks) @ inp + bias (fp32 in/out)
//   kA: blocks -> g_Ah fp16  (tiny pre-pass)
//   k2: fused GEMM: B loaded f32 from inp, converted in-register to fp16 smem;
//       C = Ah @ B + bias via mma.sync f16. CTA = 256m x 128n x 256k.
// Error: A and B each rounded once to fp16 -> global RMS rel err ~2.9e-4 (<1e-3).
// (Round 11 failed with "device busy" at harness init = infra flake; resubmitting.)

typedef unsigned int u32;

__device__ __half g_Ah[8 * 256 * 256];

__device__ __forceinline__ u32 smem_u32(const void* p) {
    u32 a;
    asm("{ .reg .u64 t; cvta.to.shared.u64 t, %1; cvt.u32.u64 %0, t; }" : "=r"(a) : "l"(p));
    return a;
}

// ---------------- kernel A: blocks -> fp16 ----------------
__global__ __launch_bounds__(256)
void split_A(const float* __restrict__ blocks)
{
    const int base = (blockIdx.x * 256 + threadIdx.x) * 4;
    float4 v = *(const float4*)(blocks + base);
    __half2 h01 = __floats2half2_rn(v.x, v.y);
    __half2 h23 = __floats2half2_rn(v.z, v.w);
    uint2 ph;
    ph.x = *reinterpret_cast<u32*>(&h01);
    ph.y = *reinterpret_cast<u32*>(&h23);
    *(uint2*)(g_Ah + base) = ph;
}

// ---------------- fused GEMM ----------------
#define BK 32
#define OFF_A  0            // A tile: 256 rows x 64B = 16 KB
#define OFF_B  16384        // B tile: 32 rows x 256B = 8 KB
#define STAGE_STRIDE 24576
#define SMEM_BYTES (2 * STAGE_STRIDE)   // 48 KB

// A tile: row-major m x k fp16, 64B rows, 4x16B chunks, XOR swizzle (verified)
__device__ __forceinline__ u32 soff(u32 r, u32 k) {
    return r * 64u + ((((k >> 3) ^ ((r >> 1) & 3u))) << 4) + ((k & 7u) << 1);
}
__device__ __forceinline__ u32 schunk(u32 r, u32 c) {
    return r * 64u + ((c ^ ((r >> 1) & 3u)) << 4);
}
// B tile: 32 k-rows x 128 n fp16, 256B rows, 16x16B chunks, chunk ^= (k&7) (verified)
__device__ __forceinline__ u32 bchunk(u32 k, u32 nc) {
    return k * 256u + ((nc ^ (k & 7u)) << 4);
}

__device__ __forceinline__ void ldsm4(u32& r0, u32& r1, u32& r2, u32& r3, u32 addr) {
    asm volatile("ldmatrix.sync.aligned.m8n8.x4.shared.b16 {%0,%1,%2,%3}, [%4];"
                 : "=r"(r0), "=r"(r1), "=r"(r2), "=r"(r3) : "r"(addr));
}
__device__ __forceinline__ void ldsm4t(u32& r0, u32& r1, u32& r2, u32& r3, u32 addr) {
    asm volatile("ldmatrix.sync.aligned.m8n8.x4.trans.shared.b16 {%0,%1,%2,%3}, [%4];"
                 : "=r"(r0), "=r"(r1), "=r"(r2), "=r"(r3) : "r"(addr));
}
__device__ __forceinline__ void mma16816(float* c, const u32* a, u32 b0, u32 b1) {
    asm volatile(
        "mma.sync.aligned.m16n8k16.row.col.f32.f16.f16.f32 "
        "{%0,%1,%2,%3}, {%4,%5,%6,%7}, {%8,%9}, {%0,%1,%2,%3};"
        : "+f"(c[0]), "+f"(c[1]), "+f"(c[2]), "+f"(c[3])
        : "r"(a[0]), "r"(a[1]), "r"(a[2]), "r"(a[3]), "r"(b0), "r"(b1));
}
__device__ __forceinline__ void cp16(u32 dst, const void* src) {
    asm volatile("cp.async.cg.shared.global [%0], [%1], 16;" :: "r"(dst), "l"(src));
}

__global__ __launch_bounds__(512, 1)
void block_linear_fused(const float* __restrict__ inp,
                        const float* __restrict__ bias,
                        float* __restrict__ out)
{
    extern __shared__ char smem[];
    const u32 sb = smem_u32(smem);

    const int tid  = threadIdx.x;
    const int lane = tid & 31;
    const int wid  = tid >> 5;
    const int wm   = wid & 7;        // 8 warp rows x 32
    const int wn   = wid >> 3;       // 2 warp cols x 64

    const int nTile = blockIdx.x;
    const int kblk  = blockIdx.y;
    const int n0    = nTile * 128;

    const __half* Ag = g_Ah + (size_t)kblk * 65536;                 // [256][256] fp16
    const float*  Bg = inp + (size_t)(kblk * 256) * 8192 + n0;      // [256][128] f32 strip
    float*        C  = out + (size_t)(kblk * 256) * 8192 + n0;
    const float*  biasp = bias + kblk * 256;

    // A loader: 512 threads, row = tid>>1 (0..255), chunks (tid&1)*2+{0,1}
    const int alr = tid >> 1;
    const int alc = (tid & 1) * 2;
    // B loader: row k = tid>>4 (0..31), 16B-chunk nc = tid&15, 8 f32 from global
    const int blr = tid >> 4;
    const int bnc = tid & 15;

    float4 bpf0, bpf1;   // B prefetch registers (8 f32)

    float acc[2][8][4];
    #pragma unroll
    for (int i = 0; i < 2; i++)
        #pragma unroll
        for (int j = 0; j < 8; j++)
            #pragma unroll
            for (int q = 0; q < 4; q++) acc[i][j][q] = 0.f;

    auto ldg_B = [&](int c) {
        const float* p = Bg + (size_t)(c * BK + blr) * 8192 + bnc * 8;
        bpf0 = *(const float4*)(p);
        bpf1 = *(const float4*)(p + 4);
    };
    auto sts_B = [&](int c) {
        __half2 h0 = __floats2half2_rn(bpf0.x, bpf0.y);
        __half2 h1 = __floats2half2_rn(bpf0.z, bpf0.w);
        __half2 h2 = __floats2half2_rn(bpf1.x, bpf1.y);
        __half2 h3 = __floats2half2_rn(bpf1.z, bpf1.w);
        uint4 o;
        o.x = *reinterpret_cast<u32*>(&h0);
        o.y = *reinterpret_cast<u32*>(&h1);
        o.z = *reinterpret_cast<u32*>(&h2);
        o.w = *reinterpret_cast<u32*>(&h3);
        *(uint4*)(smem + (c & 1) * STAGE_STRIDE + OFF_B + bchunk((u32)blr, (u32)bnc)) = o;
    };
    auto cpa_A = [&](int c) {
        const u32 st = sb + (u32)(c & 1) * STAGE_STRIDE;
        const int k0 = c * BK;
        #pragma unroll
        for (int j = 0; j < 2; ++j) {
            const int ch = alc + j;
            cp16(st + OFF_A + schunk((u32)alr, (u32)ch),
                 Ag + (size_t)alr * 256 + k0 + ch * 8);
        }
    };

    // ---- prologue ----
    ldg_B(0);
    cpa_A(0); asm volatile("cp.async.commit_group;" ::: "memory");
    sts_B(0);
    ldg_B(1);
    cpa_A(1); asm volatile("cp.async.commit_group;" ::: "memory");
    asm volatile("cp.async.wait_group 1;" ::: "memory");   // A(0) done
    __syncthreads();                                        // buf0 ready

    const u32 kl  = (u32)(((lane >> 4) << 3) + (lane & 7));
    const u32 ncl = (u32)((lane >> 3) & 1);

    #pragma unroll 1
    for (int c = 0; c < 8; ++c) {
        // ---- compute(c) on buf[c&1] ----
        const u32 buf = sb + (u32)(c & 1) * STAGE_STRIDE;
        #pragma unroll
        for (int kk = 0; kk < 2; ++kk) {
            const u32 krow = (u32)(kk * 16);
            const u32 am   = (u32)(wm * 32 + (lane & 15));
            const u32 akr  = krow + (u32)((lane >> 4) << 3);

            u32 aH[2][4], bH[4][4];
            #pragma unroll
            for (int i = 0; i < 2; i++)
                ldsm4(aH[i][0], aH[i][1], aH[i][2], aH[i][3],
                      buf + OFF_A + soff(am + i * 16, akr));
            #pragma unroll
            for (int p = 0; p < 4; p++) {
                const u32 ncb = (u32)(wn * 8 + p * 2) + ncl;
                ldsm4t(bH[p][0], bH[p][1], bH[p][2], bH[p][3],
                       buf + OFF_B + bchunk(krow + kl, ncb));
            }
            #pragma unroll
            for (int i = 0; i < 2; i++)
                #pragma unroll
                for (int p = 0; p < 4; p++) {
                    mma16816(acc[i][2*p],   aH[i], bH[p][0], bH[p][2]);
                    mma16816(acc[i][2*p+1], aH[i], bH[p][1], bH[p][3]);
                }
        }
        if (c == 7) break;
        __syncthreads();                 // all warps done reading buf[(c+1)&1] (iter c-1)

        sts_B(c + 1);                    // fill other buffer with prefetched B
        if (c + 2 < 8) {
            ldg_B(c + 2);                // next prefetch; latency covered by compute(c+1)
            cpa_A(c + 2);
            asm volatile("cp.async.commit_group;" ::: "memory");
            asm volatile("cp.async.wait_group 1;" ::: "memory");   // A(c+1) done
        } else {
            asm volatile("cp.async.wait_group 0;" ::: "memory");
        }
        __syncthreads();                 // buf[(c+1)&1] ready
    }

    // ---- epilogue: bias + store (verified mapping, wm now 0..7) ----
    #pragma unroll
    for (int i = 0; i < 2; i++) {
        const int r0 = wm * 32 + i * 16 + (lane >> 2);
        const float b0 = biasp[r0];
        const float b1 = biasp[r0 + 8];
        float* p0 = C + (size_t)r0 * 8192;
        float* p1 = C + (size_t)(r0 + 8) * 8192;
        #pragma unroll
        for (int j = 0; j < 8; j++) {
            const int col = wn * 64 + j * 8 + (lane & 3) * 2;
            *(float2*)(p0 + col) = make_float2(acc[i][j][0] + b0, acc[i][j][1] + b0);
            *(float2*)(p1 + col) = make_float2(acc[i][j][2] + b1, acc[i][j][3] + b1);
        }
    }
}

extern "C" void kernel_launch(void* const* d_in, const int* in_sizes, int n_in,
                              void* d_out, int out_size)
{
    const float* inp    = (const float*)d_in[0];   // (2048, 8192)
    const float* blocks = (const float*)d_in[1];   // (8, 256, 256)
    const float* bias   = (const float*)d_in[2];   // (2048,)
    float* out          = (float*)d_out;           // (2048, 8192)

    static int configured = 0;
    if (!configured) {
        cudaFuncSetAttribute(block_linear_fused,
                             cudaFuncAttributeMaxDynamicSharedMemorySize, SMEM_BYTES);
        configured = 1;
    }

    split_A<<<512, 256>>>(blocks);
    dim3 g2(64, 8);
    block_linear_fused<<<g2, 512, SMEM_BYTES>>>(inp, bias, out);
}